// round 2
// baseline (speedup 1.0000x reference)
#include <cuda_runtime.h>

#define BB 32
#define SS 3136
#define CC 256
#define WW 98            // SS / 32 words per channel
#define THRESH 1568      // count >= 0.5*S  -> kill pair

// scratch (no allocations allowed)
__device__ float    g_sums[BB * CC];
__device__ unsigned g_bits[BB * WW * CC];   // layout [b][w][c]
__device__ float    g_mask[BB * CC];

// ---------------------------------------------------------------- k0: zero sums
__global__ void k0_zero() {
    int t = blockIdx.x * 256 + threadIdx.x;
    if (t < BB * CC) g_sums[t] = 0.f;
}

// ---------------------------------------------------------------- k1: per-channel partial sums
// grid (49 chunks of 64 rows, B), block 256 (one thread per channel)
__global__ void k1_sums(const float* __restrict__ x) {
    int b = blockIdx.y, chunk = blockIdx.x;
    int c = threadIdx.x;
    const float* p = x + ((size_t)b * SS + (size_t)chunk * 64) * CC + c;
    float s = 0.f;
#pragma unroll 8
    for (int r = 0; r < 64; ++r) s += p[(size_t)r * CC];
    atomicAdd(&g_sums[b * CC + c], s);
}

// ---------------------------------------------------------------- k2: pack live bits
// grid (W words, B), block 256. Tile 32 rows x 256 ch through smem (coalesced),
// each thread packs the 32-bit word for its channel.
__global__ void k2_bits(const float* __restrict__ x) {
    __shared__ float tile[32 * CC];
    int b = blockIdx.y, wi = blockIdx.x;
    int t = threadIdx.x;
    const float* p = x + ((size_t)b * SS + (size_t)wi * 32) * CC;
#pragma unroll
    for (int r = 0; r < 32; ++r) tile[r * CC + t] = p[(size_t)r * CC + t];
    __syncthreads();
    float m = g_sums[b * CC + t] * (1.f / SS);
    unsigned word = 0;
#pragma unroll
    for (int r = 0; r < 32; ++r)
        word |= (tile[r * CC + t] > m) ? (1u << r) : 0u;
    g_bits[((size_t)b * WW + wi) * CC + t] = word;
}

// ---------------------------------------------------------------- k3: pairwise popcount -> kill mask
// grid (B, 4 i-tiles of 64), block 256 (ii = tid&63, jt = tid>>6).
// Whole batch's bit matrix (100,352 B) staged in dynamic smem.
__global__ void k3_pairs() {
    extern __shared__ unsigned sb[];        // WW*CC words, layout [w][c]
    __shared__ int sflag[64];
    int b = blockIdx.x, itile = blockIdx.y;
    int tid = threadIdx.x;

    for (int r = tid; r < WW * CC; r += 256)
        sb[r] = g_bits[(size_t)b * WW * CC + r];
    if (tid < 64) sflag[tid] = 0;
    __syncthreads();

    int ii = tid & 63, jt = tid >> 6;
    int i = itile * 64 + ii;
    int flag = 0;

    for (int jg = 0; jg < 8; ++jg) {
        int j0 = jt * 64 + jg * 8;
        int cnt[8];
#pragma unroll
        for (int k = 0; k < 8; ++k) cnt[k] = 0;
        for (int w = 0; w < WW; ++w) {
            unsigned mw = sb[w * CC + i];           // conflict-free (consecutive ii per warp)
#pragma unroll
            for (int k = 0; k < 8; ++k)             // broadcast reads (same addr across warp)
                cnt[k] += __popc(mw & sb[w * CC + j0 + k]);
        }
#pragma unroll
        for (int k = 0; k < 8; ++k)
            if ((j0 + k) != i && cnt[k] >= THRESH) flag = 1;
    }
    if (flag) atomicOr(&sflag[ii], 1);
    __syncthreads();
    if (tid < 64)
        g_mask[b * CC + itile * 64 + tid] = sflag[tid] ? 0.f : 1.f;
}

// ---------------------------------------------------------------- k4: apply mask (vectorized)
__global__ void k4_apply(const float4* __restrict__ x, float4* __restrict__ out) {
    size_t idx = (size_t)blockIdx.x * 256 + threadIdx.x;   // total = B*S*C/4, exact multiple
    int b = (int)(idx / ((size_t)SS * CC / 4));
    int c4 = (int)(idx & (CC / 4 - 1));
    const float4* mv = (const float4*)g_mask;
    float4 m = mv[b * (CC / 4) + c4];
    float4 v = x[idx];
    v.x *= m.x; v.y *= m.y; v.z *= m.z; v.w *= m.w;
    out[idx] = v;
}

// ----------------------------------------------------------------
extern "C" void kernel_launch(void* const* d_in, const int* in_sizes, int n_in,
                              void* d_out, int out_size) {
    const float* x = (const float*)d_in[0];
    float* out = (float*)d_out;

    cudaFuncSetAttribute(k3_pairs, cudaFuncAttributeMaxDynamicSharedMemorySize,
                         WW * CC * (int)sizeof(unsigned));

    k0_zero<<<(BB * CC + 255) / 256, 256>>>();

    dim3 g1(49, BB);
    k1_sums<<<g1, 256>>>(x);

    dim3 g2(WW, BB);
    k2_bits<<<g2, 256>>>(x);

    dim3 g3(BB, 4);
    k3_pairs<<<g3, 256, WW * CC * (int)sizeof(unsigned)>>>();

    size_t n4 = (size_t)BB * SS * CC / 4;
    k4_apply<<<(unsigned)(n4 / 256), 256>>>((const float4*)x, (float4*)out);
}